// round 12
// baseline (speedup 1.0000x reference)
#include <cuda_runtime.h>
#include <cuda_bf16.h>

#define BATCH 512
#define DIM   256
#define QUEUE 65536
#define NROWS 1024

// ---------------- device scratch (allocations are forbidden) ----------------
__device__ __align__(16) float              g_P[NROWS * DIM];       // normalized p1 (rows 0..511), p2 (512..1023)
__device__ unsigned long long               g_best[NROWS];          // packed (ordered_float<<32 | ~idx)
__device__ __align__(16) float              g_S[2 * BATCH * BATCH]; // S1 then S2

// ---------------- kernel 1: L2 normalize + init ----------------
__global__ void __launch_bounds__(256) norm_kernel(const float* __restrict__ p1,
                                                   const float* __restrict__ p2,
                                                   float* __restrict__ outq) {
    int row = blockIdx.x, t = threadIdx.x;
    const float* src = (row < BATCH) ? (p1 + (size_t)row * DIM)
                                     : (p2 + (size_t)(row - BATCH) * DIM);
    float x = src[t];
    float s = x * x;
    #pragma unroll
    for (int off = 16; off; off >>= 1) s += __shfl_xor_sync(0xFFFFFFFFu, s, off);
    __shared__ float ws[8];
    if ((t & 31) == 0) ws[t >> 5] = s;
    __syncthreads();
    float sum = 0.f;
    #pragma unroll
    for (int i = 0; i < 8; i++) sum += ws[i];
    float sc = rsqrtf(fmaxf(sum, 1e-12f));
    float y = x * sc;
    g_P[row * DIM + t] = y;
    if (row < BATCH) outq[(size_t)row * DIM + t] = y;  // new_queue front = p1 normalized
    if (t == 0) g_best[row] = 0ULL;
}

// ---------------- kernel 2: exact fp32 similarity + argmax (FFMA2) ----------------
// grid (512, 8): bx = 128-row queue tile, by = 128-row P group. block (16,16).
// P row of thread (i):  by*128 + ty*8 + i    (blocked  -> conflict-free a loads)
// Q row of thread (j):  bx*128 + tx + 16*j   (strided  -> conflict-free b loads)
// acc[i][j] packs (sum over even k, sum over odd k) as f32x2; dot = lo + hi.
__global__ void __launch_bounds__(256) simargmax_kernel(const float* __restrict__ fq) {
    __shared__ float Ps[128][34];
    __shared__ float Qs[128][34];
    const int tx = threadIdx.x, ty = threadIdx.y;
    const int t = ty * 16 + tx;
    const int bx = blockIdx.x, by = blockIdx.y;

    unsigned long long acc[8][8];
    #pragma unroll
    for (int i = 0; i < 8; i++)
        #pragma unroll
        for (int j = 0; j < 8; j++) acc[i][j] = 0ULL;

    for (int kc = 0; kc < DIM; kc += 32) {
        __syncthreads();
        #pragma unroll
        for (int l = 0; l < 4; ++l) {
            int idx = l * 256 + t;
            int row = idx >> 3;
            int k4  = (idx & 7) * 4;
            float4 v = *(const float4*)&g_P[(size_t)(by * 128 + row) * DIM + kc + k4];
            Ps[row][k4 + 0] = v.x; Ps[row][k4 + 1] = v.y;
            Ps[row][k4 + 2] = v.z; Ps[row][k4 + 3] = v.w;
            float4 w = *(const float4*)&fq[(size_t)(bx * 128 + row) * DIM + kc + k4];
            Qs[row][k4 + 0] = w.x; Qs[row][k4 + 1] = w.y;
            Qs[row][k4 + 2] = w.z; Qs[row][k4 + 3] = w.w;
        }
        __syncthreads();
        #pragma unroll
        for (int k = 0; k < 32; k += 2) {
            unsigned long long a2[8], b2[8];
            #pragma unroll
            for (int i = 0; i < 8; i++)
                a2[i] = *(const unsigned long long*)&Ps[ty * 8 + i][k];
            #pragma unroll
            for (int j = 0; j < 8; j++)
                b2[j] = *(const unsigned long long*)&Qs[tx + 16 * j][k];
            #pragma unroll
            for (int i = 0; i < 8; i++)
                #pragma unroll
                for (int j = 0; j < 8; j++)
                    asm("fma.rn.f32x2 %0, %1, %2, %0;"
                        : "+l"(acc[i][j]) : "l"(a2[i]), "l"(b2[j]));
        }
    }

    // epilogue: per-P-row packed argmax, reduce across the 16 tx lanes, atomicMax
    #pragma unroll
    for (int i = 0; i < 8; i++) {
        unsigned long long best = 0ULL;
        #pragma unroll
        for (int j = 0; j < 8; j++) {
            float lo = __uint_as_float((unsigned)(acc[i][j] & 0xFFFFFFFFu));
            float hi = __uint_as_float((unsigned)(acc[i][j] >> 32));
            float d  = lo + hi;
            unsigned u   = __float_as_uint(d);
            unsigned key = (u & 0x80000000u) ? ~u : (u | 0x80000000u);
            unsigned q   = (unsigned)(bx * 128 + tx + 16 * j);
            unsigned long long pk = ((unsigned long long)key << 32) | (unsigned)(~q);
            best = (pk > best) ? pk : best;
        }
        #pragma unroll
        for (int off = 8; off; off >>= 1) {
            unsigned long long o = __shfl_xor_sync(0xFFFFFFFFu, best, off);
            best = (o > best) ? o : best;
        }
        if (tx == 0) atomicMax(&g_best[by * 128 + ty * 8 + i], best);
    }
}

// ---------------- kernel 3: logits S_z = NN_z . P_other^T / T ----------------
// grid (8, 8, 2): bx = col tile, by = row tile, z = side. block (16,16), 4x4 micro.
__global__ void __launch_bounds__(256) logits_kernel(const float* __restrict__ fq) {
    __shared__ float As[64][34];
    __shared__ float Bs[64][34];
    const int tx = threadIdx.x, ty = threadIdx.y;
    const int t = ty * 16 + tx;
    const int bx = blockIdx.x, by = blockIdx.y, z = blockIdx.z;
    const int zoff = z ? 0 : BATCH;  // z=0 -> p2 rows, z=1 -> p1 rows

    float acc[4][4];
    #pragma unroll
    for (int i = 0; i < 4; i++)
        #pragma unroll
        for (int j = 0; j < 4; j++) acc[i][j] = 0.f;

    for (int kc = 0; kc < DIM; kc += 32) {
        __syncthreads();
        #pragma unroll
        for (int l = 0; l < 2; ++l) {
            int idx = l * 256 + t;
            int row = idx >> 3;
            int k4  = (idx & 7) * 4;
            unsigned q = ~(unsigned)(g_best[z * BATCH + by * 64 + row] & 0xFFFFFFFFu);
            float4 v = *(const float4*)&fq[(size_t)q * DIM + kc + k4];
            As[row][k4 + 0] = v.x; As[row][k4 + 1] = v.y;
            As[row][k4 + 2] = v.z; As[row][k4 + 3] = v.w;
            float4 w = *(const float4*)&g_P[(size_t)(zoff + bx * 64 + row) * DIM + kc + k4];
            Bs[row][k4 + 0] = w.x; Bs[row][k4 + 1] = w.y;
            Bs[row][k4 + 2] = w.z; Bs[row][k4 + 3] = w.w;
        }
        __syncthreads();
        #pragma unroll
        for (int k = 0; k < 32; k++) {
            float a[4], b[4];
            #pragma unroll
            for (int i = 0; i < 4; i++) a[i] = As[ty * 4 + i][k];
            #pragma unroll
            for (int j = 0; j < 4; j++) b[j] = Bs[tx + 16 * j][k];
            #pragma unroll
            for (int i = 0; i < 4; i++)
                #pragma unroll
                for (int j = 0; j < 4; j++) acc[i][j] = fmaf(a[i], b[j], acc[i][j]);
        }
    }
    #pragma unroll
    for (int i = 0; i < 4; i++) {
        int brow = by * 64 + ty * 4 + i;
        #pragma unroll
        for (int j = 0; j < 4; j++) {
            int ccol = bx * 64 + tx + 16 * j;
            g_S[((size_t)z * BATCH + brow) * BATCH + ccol] = acc[i][j] * 10.0f;  // 1/T
        }
    }
}

// ---------------- kernel 4: loss rows (row / column log-softmax) ----------------
__global__ void __launch_bounds__(512) loss_kernel(float* __restrict__ out) {
    const int r = blockIdx.x, t = threadIdx.x;
    const int g = r >> 9, i = r & 511;
    const int z = g >> 1, colside = g & 1;
    const float* S = g_S + (size_t)z * BATCH * BATCH;
    float v = colside ? S[(size_t)t * BATCH + i] : S[(size_t)i * BATCH + t];
    float diag = S[(size_t)i * BATCH + i];

    __shared__ float red[16];
    float m = v;
    #pragma unroll
    for (int off = 16; off; off >>= 1) m = fmaxf(m, __shfl_xor_sync(0xFFFFFFFFu, m, off));
    if ((t & 31) == 0) red[t >> 5] = m;
    __syncthreads();
    if (t == 0) {
        float mm = red[0];
        #pragma unroll
        for (int w = 1; w < 16; w++) mm = fmaxf(mm, red[w]);
        red[0] = mm;
    }
    __syncthreads();
    m = red[0];
    __syncthreads();

    float e = __expf(v - m);
    #pragma unroll
    for (int off = 16; off; off >>= 1) e += __shfl_xor_sync(0xFFFFFFFFu, e, off);
    if ((t & 31) == 0) red[t >> 5] = e;
    __syncthreads();
    if (t == 0) {
        float sum = 0.f;
        #pragma unroll
        for (int w = 0; w < 16; w++) sum += red[w];
        out[r] = m + logf(sum) - diag;
    }
}

// ---------------- launch ----------------
extern "C" void kernel_launch(void* const* d_in, const int* in_sizes, int n_in,
                              void* d_out, int out_size) {
    const float* p1 = (const float*)d_in[0];
    const float* p2 = (const float*)d_in[1];
    const float* fq = (const float*)d_in[2];
    float* out = (float*)d_out;

    // FIFO queue shift: new_queue rows [512, 65536) = feature_queue[0 : 65024)
    cudaMemcpyAsync(out + 2048 + (size_t)BATCH * DIM, fq,
                    (size_t)(QUEUE - BATCH) * DIM * sizeof(float),
                    cudaMemcpyDeviceToDevice, 0);

    norm_kernel<<<NROWS, 256>>>(p1, p2, out + 2048);
    simargmax_kernel<<<dim3(QUEUE / 128, NROWS / 128), dim3(16, 16)>>>(fq);
    logits_kernel<<<dim3(8, 8, 2), dim3(16, 16)>>>(fq);
    loss_kernel<<<2048, 512>>>(out);
}